// round 6
// baseline (speedup 1.0000x reference)
#include <cuda_runtime.h>
#include <cstdint>

#define G_TOT   1024
#define WSZ     16
#define HDIM    16
#define B_ROWS  8192
#define GTILE   64                    // groups per CTA column tile
#define HSPLIT  4                     // threads per group along H (4 h each)
#define BLOCK   (GTILE * HSPLIT)      // 256 threads
#define CHUNK_ROWS 8
#define STAGES  3
#define ROWSTRIDE 16384               // floats per x/out row (G*16)
#define SLICE   (GTILE * WSZ)         // 1024 floats per row-slice (4KB)
#define STAGE_FLOATS (CHUNK_ROWS * SLICE)               // 8192 floats (32KB)
#define STAGE_BYTES  (STAGE_FLOATS * 4)
#define SMEM_BYTES   (STAGES * STAGE_BYTES)             // 96KB
#define CHUNKS_PER_GT (B_ROWS / CHUNK_ROWS)             // 1024
#define NCHUNKS_TOT   (CHUNKS_PER_GT * (G_TOT / GTILE)) // 16384

__device__ __forceinline__ unsigned long long pack2(float lo, float hi) {
    unsigned long long r;
    asm("mov.b64 %0, {%1, %2};" : "=l"(r) : "f"(lo), "f"(hi));
    return r;
}
__device__ __forceinline__ void unpack2(unsigned long long v, float& lo, float& hi) {
    asm("mov.b64 {%0, %1}, %2;" : "=f"(lo), "=f"(hi) : "l"(v));
}
// d = a * b + d  (packed f32x2 — ptxas never auto-emits FFMA2)
__device__ __forceinline__ void ffma2(unsigned long long& d,
                                      unsigned long long a, unsigned long long b) {
    asm("fma.rn.f32x2 %0, %1, %2, %0;" : "+l"(d) : "l"(a), "l"(b));
}
__device__ __forceinline__ uint32_t smem_u32(const void* p) {
    return (uint32_t)__cvta_generic_to_shared(p);
}
__device__ __forceinline__ void cp_async16(uint32_t dst, const void* src) {
    asm volatile("cp.async.cg.shared.global [%0], [%1], 16;" :: "r"(dst), "l"(src));
}

__global__ void __launch_bounds__(BLOCK, 2)
bd_kernel(const float* __restrict__ x, const float* __restrict__ W,
          float* __restrict__ out)
{
    extern __shared__ float xs[];   // 96 KB: 3 stages x (8 rows x 4 u-planes x 64 groups x 16B)

    const int tid = threadIdx.x;
    const int hq  = tid & (HSPLIT - 1);   // h quad: h = hq*4 .. hq*4+3
    const int gl  = tid >> 2;             // local group (0..63)

    // flattened persistent split: single wave, balanced ±1 chunk
    const int c0 = (int)((long long)blockIdx.x       * NCHUNKS_TOT / gridDim.x);
    const int c1 = (int)((long long)(blockIdx.x + 1) * NCHUNKS_TOT / gridDim.x);
    const int n  = c1 - c0;

    // ---- loader: transpose into [row][u-plane][group] layout, 8 cp.async/chunk
    // thread t handles global 16B unit t of each row j: gl_u = t>>2, u = t&3
    // smem dst: row j at j*4096B; plane u at u*1024B; group at gl_u*16B
    const uint32_t dst0 = smem_u32(xs) + (tid & 3) * 1024 + (tid >> 2) * 16;

    int lgt  = c0 >> 10;                               // c / CHUNKS_PER_GT
    int lrow = (c0 & (CHUNKS_PER_GT - 1)) * CHUNK_ROWS;
    const float* lsrcT = x + (size_t)lrow * ROWSTRIDE + lgt * SLICE + tid * 4;
    int lslot = 0;

    auto issue_load = [&]() {
        const uint32_t d = dst0 + lslot * STAGE_BYTES;
#pragma unroll
        for (int j = 0; j < CHUNK_ROWS; ++j)
            cp_async16(d + j * 4096, lsrcT + (size_t)j * ROWSTRIDE);
        asm volatile("cp.async.commit_group;");
        lrow  += CHUNK_ROWS;
        lsrcT += CHUNK_ROWS * ROWSTRIDE;
        if (lrow == B_ROWS) {                          // <=1 crossing per CTA
            lrow = 0; ++lgt;
            lsrcT = x + lgt * SLICE + tid * 4;
        }
        if (++lslot == STAGES) lslot = 0;
    };

    for (int i = 0; i < STAGES - 1; ++i) {
        if (i < n) issue_load();
        else       asm volatile("cp.async.commit_group;");
    }

    // ---- compute state ----
    int cgt  = c0 >> 10;
    int crow = (c0 & (CHUNKS_PER_GT - 1)) * CHUNK_ROWS;
    float* optrT = out + (size_t)crow * ROWSTRIDE
                       + (cgt * GTILE + gl) * HDIM + hq * 4;
    int cslot = 0;
    int need_w = 1;
    unsigned long long w2[WSZ / 2][4];    // [k-pair][local h] = (W[2k2][h], W[2k2+1][h])

    for (int k = 0; k < n; ++k) {
        if (need_w) {                                  // rare: start + <=1 crossing
            need_w = 0;
            const float* wg = W + (size_t)(cgt * GTILE + gl) * (WSZ * HDIM) + hq * 4;
#pragma unroll
            for (int k2 = 0; k2 < WSZ / 2; ++k2) {
                float4 a = *(const float4*)(wg + (2 * k2)     * HDIM);
                float4 b = *(const float4*)(wg + (2 * k2 + 1) * HDIM);
                w2[k2][0] = pack2(a.x, b.x);
                w2[k2][1] = pack2(a.y, b.y);
                w2[k2][2] = pack2(a.z, b.z);
                w2[k2][3] = pack2(a.w, b.w);
            }
        }

        asm volatile("cp.async.wait_group %0;" :: "n"(STAGES - 2));
        __syncthreads();   // chunk k resident; oldest slot's reads done at k-1

        if (k + STAGES - 1 < n) issue_load();
        else asm volatile("cp.async.commit_group;");

        // consumer: 4 conflict-free LDS.128 per row (warp = 8 consecutive 16B/plane)
        const float* xb = xs + cslot * STAGE_FLOATS + gl * 4;   // plane offset +256 floats
#pragma unroll
        for (int rl = 0; rl < CHUNK_ROWS; ++rl) {
            const float* xr = xb + rl * SLICE;
            ulonglong2 p0 = *(const ulonglong2*)(xr);         // u=0: k 0..3
            ulonglong2 p1 = *(const ulonglong2*)(xr + 256);   // u=1: k 4..7
            ulonglong2 p2 = *(const ulonglong2*)(xr + 512);   // u=2: k 8..11
            ulonglong2 p3 = *(const ulonglong2*)(xr + 768);   // u=3: k 12..15
            unsigned long long xv[8] = {p0.x, p0.y, p1.x, p1.y,
                                        p2.x, p2.y, p3.x, p3.y};
            unsigned long long a0 = 0ull, a1 = 0ull, a2 = 0ull, a3 = 0ull;
#pragma unroll
            for (int k2 = 0; k2 < 8; ++k2) {
                ffma2(a0, xv[k2], w2[k2][0]);
                ffma2(a1, xv[k2], w2[k2][1]);
                ffma2(a2, xv[k2], w2[k2][2]);
                ffma2(a3, xv[k2], w2[k2][3]);
            }
            float l, h;
            float4 o;
            unpack2(a0, l, h); o.x = fmaxf(l + h, 0.0f);
            unpack2(a1, l, h); o.y = fmaxf(l + h, 0.0f);
            unpack2(a2, l, h); o.z = fmaxf(l + h, 0.0f);
            unpack2(a3, l, h); o.w = fmaxf(l + h, 0.0f);
            *(float4*)(optrT + (size_t)rl * ROWSTRIDE) = o;   // 1 STG.128 / 4 outputs
        }

        crow  += CHUNK_ROWS;
        optrT += CHUNK_ROWS * ROWSTRIDE;
        if (crow == B_ROWS) {
            crow = 0; ++cgt; need_w = 1;
            optrT = out + (size_t)(cgt * GTILE + gl) * HDIM + hq * 4;
        }
        if (++cslot == STAGES) cslot = 0;
    }
}

extern "C" void kernel_launch(void* const* d_in, const int* in_sizes, int n_in,
                              void* d_out, int out_size) {
    const float* x = (const float*)d_in[0];   // (8192, 16384) f32
    const float* W = (const float*)d_in[1];   // (1024, 16, 16) f32
    float* out = (float*)d_out;               // (8192, 16384) f32

    cudaFuncSetAttribute(bd_kernel,
                         cudaFuncAttributeMaxDynamicSharedMemorySize, SMEM_BYTES);

    int sms = 148;
    cudaDeviceGetAttribute(&sms, cudaDevAttrMultiProcessorCount, 0);
    dim3 grid(sms * 2);                        // one wave at occ=2 (96KB smem/CTA)
    bd_kernel<<<grid, BLOCK, SMEM_BYTES>>>(x, W, out);
}

// round 7
// speedup vs baseline: 1.0234x; 1.0234x over previous
#include <cuda_runtime.h>
#include <cstdint>

#define G_TOT   1024
#define WSZ     16
#define HDIM    16
#define B_ROWS  8192
#define GTILE   32                    // groups per CTA column tile
#define HSPLIT  8                     // threads per group along H (2 h each)
#define BLOCK   (GTILE * HSPLIT)      // 256 threads
#define CHUNK_ROWS 8
#define STAGES  3
#define ROWSTRIDE 16384               // floats per x/out row (G*16)
#define SLICE   (GTILE * WSZ)         // 512 floats per row-slice (2KB)
#define STAGE_FLOATS (CHUNK_ROWS * SLICE)               // 4096 floats (16KB)
#define STAGE_BYTES  (STAGE_FLOATS * 4)
#define SMEM_BYTES   (STAGES * STAGE_BYTES)             // 48KB
#define CHUNKS_PER_GT (B_ROWS / CHUNK_ROWS)             // 1024
#define NCHUNKS_TOT   (CHUNKS_PER_GT * (G_TOT / GTILE)) // 32768

__device__ __forceinline__ unsigned long long pack2(float lo, float hi) {
    unsigned long long r;
    asm("mov.b64 %0, {%1, %2};" : "=l"(r) : "f"(lo), "f"(hi));
    return r;
}
__device__ __forceinline__ void unpack2(unsigned long long v, float& lo, float& hi) {
    asm("mov.b64 {%0, %1}, %2;" : "=f"(lo), "=f"(hi) : "l"(v));
}
// d = a * b + d  (packed f32x2 — ptxas never auto-emits FFMA2)
__device__ __forceinline__ void ffma2(unsigned long long& d,
                                      unsigned long long a, unsigned long long b) {
    asm("fma.rn.f32x2 %0, %1, %2, %0;" : "+l"(d) : "l"(a), "l"(b));
}
__device__ __forceinline__ uint32_t smem_u32(const void* p) {
    return (uint32_t)__cvta_generic_to_shared(p);
}
__device__ __forceinline__ void cp_async16(uint32_t dst, const void* src) {
    asm volatile("cp.async.cg.shared.global [%0], [%1], 16;" :: "r"(dst), "l"(src));
}

__global__ void __launch_bounds__(BLOCK, 3)
bd_kernel(const float* __restrict__ x, const float* __restrict__ W,
          float* __restrict__ out)
{
    // 48 KB: 3 stages x [8 rows][4 k-quad planes][32 groups x 16B]
    __shared__ float xs[STAGES * STAGE_FLOATS];

    const int tid = threadIdx.x;
    const int hq  = tid & (HSPLIT - 1);   // h-pair (0..7)
    const int gl  = tid >> 3;             // local group (0..31)

    // flattened persistent split: single wave, balanced ±1 chunk
    const int c0 = (int)((long long)blockIdx.x       * NCHUNKS_TOT / gridDim.x);
    const int c1 = (int)((long long)(blockIdx.x + 1) * NCHUNKS_TOT / gridDim.x);
    const int n  = c1 - c0;

    // ---- loader: transposing placement. 128 16B units per row; thread handles
    // unit (tid&127) of rows (tid>>7)+{0,2,4,6}. Unit = group g (bits 6:2) and
    // k-quad u (bits 1:0); dst = row*2048B + u*512B + g*16B. Global unchanged.
    const int lrl  = tid >> 7;
    const uint32_t dst0 = smem_u32(xs) + lrl * 2048
                          + (tid & 3) * 512 + ((tid & 127) >> 2) * 16;

    int lgt  = c0 >> 10;                               // c / CHUNKS_PER_GT
    int lrow = (c0 & (CHUNKS_PER_GT - 1)) * CHUNK_ROWS;
    const float* lsrcT = x + (size_t)(lrow + lrl) * ROWSTRIDE
                           + lgt * SLICE + (tid & 127) * 4;
    int lslot = 0;

    auto issue_load = [&]() {
        const uint32_t d = dst0 + lslot * STAGE_BYTES;
        cp_async16(d,         lsrcT);
        cp_async16(d + 4096,  lsrcT + 2 * ROWSTRIDE);
        cp_async16(d + 8192,  lsrcT + 4 * ROWSTRIDE);
        cp_async16(d + 12288, lsrcT + 6 * ROWSTRIDE);
        asm volatile("cp.async.commit_group;");
        lrow  += CHUNK_ROWS;
        lsrcT += CHUNK_ROWS * ROWSTRIDE;
        if (lrow == B_ROWS) {                          // <=1 crossing per CTA
            lrow = 0; ++lgt;
            lsrcT = x + (size_t)lrl * ROWSTRIDE + lgt * SLICE + (tid & 127) * 4;
        }
        if (++lslot == STAGES) lslot = 0;
    };

    for (int i = 0; i < STAGES - 1; ++i) {
        if (i < n) issue_load();
        else       asm volatile("cp.async.commit_group;");
    }

    // ---- compute state (incremental) ----
    int cgt  = c0 >> 10;
    int crow = (c0 & (CHUNKS_PER_GT - 1)) * CHUNK_ROWS;
    float* optrT = out + (size_t)crow * ROWSTRIDE
                       + (cgt * GTILE + gl) * HDIM + hq * 2;
    int cslot = 0;
    int need_w = 1;
    unsigned long long w2[WSZ / 2][2];

    for (int k = 0; k < n; ++k) {
        if (need_w) {                                  // rare: start + <=1 crossing
            need_w = 0;
            const float* wg = W + (size_t)(cgt * GTILE + gl) * (WSZ * HDIM) + hq * 2;
#pragma unroll
            for (int k2 = 0; k2 < WSZ / 2; ++k2) {
                float2 a = *(const float2*)(wg + (2 * k2)     * HDIM);
                float2 b = *(const float2*)(wg + (2 * k2 + 1) * HDIM);
                w2[k2][0] = pack2(a.x, b.x);
                w2[k2][1] = pack2(a.y, b.y);
            }
        }

        asm volatile("cp.async.wait_group %0;" :: "n"(STAGES - 2));
        __syncthreads();   // chunk k resident; oldest slot's reads done at k-1

        if (k + STAGES - 1 < n) issue_load();
        else asm volatile("cp.async.commit_group;");

        // consumer: 4 LDS.128/row, each warp-contiguous 64B -> conflict-free
        const float* xb = xs + cslot * STAGE_FLOATS + gl * 4;
#pragma unroll
        for (int rl = 0; rl < CHUNK_ROWS; ++rl) {
            const float* xr = xb + rl * SLICE;
            ulonglong2 p0 = *(const ulonglong2*)(xr);         // u=0: k 0..3
            ulonglong2 p1 = *(const ulonglong2*)(xr + 128);   // u=1: k 4..7
            ulonglong2 p2 = *(const ulonglong2*)(xr + 256);   // u=2: k 8..11
            ulonglong2 p3 = *(const ulonglong2*)(xr + 384);   // u=3: k 12..15
            unsigned long long a0 = 0ull, a1 = 0ull;
            ffma2(a0, p0.x, w2[0][0]); ffma2(a1, p0.x, w2[0][1]);
            ffma2(a0, p0.y, w2[1][0]); ffma2(a1, p0.y, w2[1][1]);
            ffma2(a0, p1.x, w2[2][0]); ffma2(a1, p1.x, w2[2][1]);
            ffma2(a0, p1.y, w2[3][0]); ffma2(a1, p1.y, w2[3][1]);
            ffma2(a0, p2.x, w2[4][0]); ffma2(a1, p2.x, w2[4][1]);
            ffma2(a0, p2.y, w2[5][0]); ffma2(a1, p2.y, w2[5][1]);
            ffma2(a0, p3.x, w2[6][0]); ffma2(a1, p3.x, w2[6][1]);
            ffma2(a0, p3.y, w2[7][0]); ffma2(a1, p3.y, w2[7][1]);
            float l0, h0, l1, h1;
            unpack2(a0, l0, h0);
            unpack2(a1, l1, h1);
            float2 o;
            o.x = fmaxf(l0 + h0, 0.0f);     // k-pair horizontal reduce + ReLU
            o.y = fmaxf(l1 + h1, 0.0f);
            *(float2*)(optrT + (size_t)rl * ROWSTRIDE) = o;
        }

        crow  += CHUNK_ROWS;
        optrT += CHUNK_ROWS * ROWSTRIDE;
        if (crow == B_ROWS) {
            crow = 0; ++cgt; need_w = 1;
            optrT = out + (size_t)(cgt * GTILE + gl) * HDIM + hq * 2;
        }
        if (++cslot == STAGES) cslot = 0;
    }
}

extern "C" void kernel_launch(void* const* d_in, const int* in_sizes, int n_in,
                              void* d_out, int out_size) {
    const float* x = (const float*)d_in[0];   // (8192, 16384) f32
    const float* W = (const float*)d_in[1];   // (1024, 16, 16) f32
    float* out = (float*)d_out;               // (8192, 16384) f32

    int sms = 148;
    cudaDeviceGetAttribute(&sms, cudaDevAttrMultiProcessorCount, 0);
    dim3 grid(sms * 3);                        // exactly one wave at occ=3
    bd_kernel<<<grid, BLOCK>>>(x, W, out);
}

// round 8
// speedup vs baseline: 1.4822x; 1.4483x over previous
#include <cuda_runtime.h>
#include <cstdint>

#define G_TOT   1024
#define WSZ     16
#define HDIM    16
#define B_ROWS  8192
#define GTILE   32                    // groups per CTA column tile
#define HSPLIT  8                     // threads per group along H (2 h each)
#define BLOCK   (GTILE * HSPLIT)      // 256 threads
#define CHUNK_ROWS 8
#define STAGES  4
#define ROWSTRIDE 16384               // floats per x/out row (G*16)
#define SLICE   (GTILE * WSZ)         // 512 floats per row-slice
#define STAGE_FLOATS (CHUNK_ROWS * SLICE)               // 4096 floats (16KB)
#define STAGE_BYTES  (STAGE_FLOATS * 4)
#define SMEM_BYTES   (STAGES * STAGE_BYTES)             // 64KB
#define CHUNKS_PER_GT (B_ROWS / CHUNK_ROWS)             // 1024
#define NCHUNKS_TOT   (CHUNKS_PER_GT * (G_TOT / GTILE)) // 32768

__device__ __forceinline__ unsigned long long pack2(float lo, float hi) {
    unsigned long long r;
    asm("mov.b64 %0, {%1, %2};" : "=l"(r) : "f"(lo), "f"(hi));
    return r;
}
__device__ __forceinline__ void unpack2(unsigned long long v, float& lo, float& hi) {
    asm("mov.b64 {%0, %1}, %2;" : "=f"(lo), "=f"(hi) : "l"(v));
}
// d = a * b + d  (packed f32x2 — ptxas never auto-emits FFMA2)
__device__ __forceinline__ void ffma2(unsigned long long& d,
                                      unsigned long long a, unsigned long long b) {
    asm("fma.rn.f32x2 %0, %1, %2, %0;" : "+l"(d) : "l"(a), "l"(b));
}
__device__ __forceinline__ uint32_t smem_u32(const void* p) {
    return (uint32_t)__cvta_generic_to_shared(p);
}
__device__ __forceinline__ void cp_async16(uint32_t dst, const void* src) {
    asm volatile("cp.async.cg.shared.global [%0], [%1], 16;" :: "r"(dst), "l"(src));
}

__global__ void __launch_bounds__(BLOCK, 3)
bd_kernel(const float* __restrict__ x, const float* __restrict__ W,
          float* __restrict__ out)
{
    extern __shared__ float xs[];   // 64 KB: 4 stages x 8 rows x 512 floats

    const int tid = threadIdx.x;
    const int hq  = tid & (HSPLIT - 1);
    const int gl  = tid >> 3;

    // flattened persistent split: single wave, balanced ±1 chunk
    const int c0 = (int)((long long)blockIdx.x       * NCHUNKS_TOT / gridDim.x);
    const int c1 = (int)((long long)(blockIdx.x + 1) * NCHUNKS_TOT / gridDim.x);
    const int n  = c1 - c0;

    // ---- loader: per-thread constants -> 4 immediate-offset cp.async per chunk
    const int lrl  = tid >> 7;                         // base row within chunk (0/1)
    const uint32_t dst0 = smem_u32(xs) + lrl * 2048 + (tid & 127) * 16;

    int lgt  = c0 >> 10;
    int lrow = (c0 & (CHUNKS_PER_GT - 1)) * CHUNK_ROWS;
    const float* lsrcT = x + (size_t)(lrow + lrl) * ROWSTRIDE
                           + lgt * SLICE + (tid & 127) * 4;
    int lslot = 0;

    auto issue_load = [&]() {
        const uint32_t d = dst0 + lslot * STAGE_BYTES;
        cp_async16(d,         lsrcT);
        cp_async16(d + 4096,  lsrcT + 2 * ROWSTRIDE);
        cp_async16(d + 8192,  lsrcT + 4 * ROWSTRIDE);
        cp_async16(d + 12288, lsrcT + 6 * ROWSTRIDE);
        asm volatile("cp.async.commit_group;");
        lrow  += CHUNK_ROWS;
        lsrcT += CHUNK_ROWS * ROWSTRIDE;
        if (lrow == B_ROWS) {                          // <=1 crossing per CTA
            lrow = 0; ++lgt;
            lsrcT = x + (size_t)lrl * ROWSTRIDE + lgt * SLICE + (tid & 127) * 4;
        }
        if (++lslot == STAGES) lslot = 0;
    };

    // prologue: fill pipeline (commit empty groups to keep counts aligned)
    for (int i = 0; i < STAGES - 1; ++i) {
        if (i < n) issue_load();
        else       asm volatile("cp.async.commit_group;");
    }

    // ---- compute state (incremental) ----
    int cgt  = c0 >> 10;
    int crow = (c0 & (CHUNKS_PER_GT - 1)) * CHUNK_ROWS;
    float* optrT = out + (size_t)crow * ROWSTRIDE
                       + (cgt * GTILE + gl) * HDIM + hq * 2;
    int cslot = 0;
    int need_w = 1;
    unsigned long long w2[WSZ / 2][2];

    for (int k = 0; k < n; ++k) {
        if (need_w) {                                  // rare: start + <=1 crossing
            need_w = 0;
            const float* wg = W + (size_t)(cgt * GTILE + gl) * (WSZ * HDIM) + hq * 2;
#pragma unroll
            for (int k2 = 0; k2 < WSZ / 2; ++k2) {
                float2 a = *(const float2*)(wg + (2 * k2)     * HDIM);
                float2 b = *(const float2*)(wg + (2 * k2 + 1) * HDIM);
                w2[k2][0] = pack2(a.x, b.x);
                w2[k2][1] = pack2(a.y, b.y);
            }
        }

        asm volatile("cp.async.wait_group %0;" :: "n"(STAGES - 2));
        __syncthreads();   // chunk k resident; oldest slot's reads done at k-1

        if (k + STAGES - 1 < n) issue_load();
        else asm volatile("cp.async.commit_group;");

        const float* xb = xs + cslot * STAGE_FLOATS + gl * WSZ;
#pragma unroll
        for (int rl = 0; rl < CHUNK_ROWS; ++rl) {
            const ulonglong2* xq = (const ulonglong2*)(xb + rl * SLICE);
            ulonglong2 q0 = xq[0], q1 = xq[1], q2 = xq[2], q3 = xq[3];
            unsigned long long a0 = 0ull, a1 = 0ull;
            ffma2(a0, q0.x, w2[0][0]); ffma2(a1, q0.x, w2[0][1]);
            ffma2(a0, q0.y, w2[1][0]); ffma2(a1, q0.y, w2[1][1]);
            ffma2(a0, q1.x, w2[2][0]); ffma2(a1, q1.x, w2[2][1]);
            ffma2(a0, q1.y, w2[3][0]); ffma2(a1, q1.y, w2[3][1]);
            ffma2(a0, q2.x, w2[4][0]); ffma2(a1, q2.x, w2[4][1]);
            ffma2(a0, q2.y, w2[5][0]); ffma2(a1, q2.y, w2[5][1]);
            ffma2(a0, q3.x, w2[6][0]); ffma2(a1, q3.x, w2[6][1]);
            ffma2(a0, q3.y, w2[7][0]); ffma2(a1, q3.y, w2[7][1]);
            float l0, h0, l1, h1;
            unpack2(a0, l0, h0);
            unpack2(a1, l1, h1);
            float2 o;
            o.x = fmaxf(l0 + h0, 0.0f);     // k-pair horizontal reduce + ReLU
            o.y = fmaxf(l1 + h1, 0.0f);
            *(float2*)(optrT + (size_t)rl * ROWSTRIDE) = o;  // immediate offsets
        }

        crow  += CHUNK_ROWS;
        optrT += CHUNK_ROWS * ROWSTRIDE;
        if (crow == B_ROWS) {
            crow = 0; ++cgt; need_w = 1;
            optrT = out + (size_t)(cgt * GTILE + gl) * HDIM + hq * 2;
        }
        if (++cslot == STAGES) cslot = 0;
    }
}

extern "C" void kernel_launch(void* const* d_in, const int* in_sizes, int n_in,
                              void* d_out, int out_size) {
    const float* x = (const float*)d_in[0];   // (8192, 16384) f32
    const float* W = (const float*)d_in[1];   // (1024, 16, 16) f32
    float* out = (float*)d_out;               // (8192, 16384) f32

    cudaFuncSetAttribute(bd_kernel,
                         cudaFuncAttributeMaxDynamicSharedMemorySize, SMEM_BYTES);

    int sms = 148;
    cudaDeviceGetAttribute(&sms, cudaDevAttrMultiProcessorCount, 0);
    dim3 grid(sms * 3);                        // exactly one wave at occ=3
    bd_kernel<<<grid, BLOCK, SMEM_BYTES>>>(x, W, out);
}